// round 7
// baseline (speedup 1.0000x reference)
#include <cuda_runtime.h>
#include <math.h>
#include <stdint.h>

// Problem constants
#define BATCH 2
#define SLEN  4096
#define DMODEL 768
#define NH    12
#define HD    64
#define MROWS (BATCH * SLEN)        // 8192

// ---------------- scratch (device globals; allocation-free) ----------------
__device__ float g_qh[BATCH * NH * SLEN * HD];   // [B,H,S,HD] (tf32-rounded, pre-scaled)
__device__ float g_kh[BATCH * NH * SLEN * HD];   // tf32-rounded
__device__ float g_vh[BATCH * NH * SLEN * HD];   // tf32-rounded
__device__ float g_feats[BATCH * SLEN * DMODEL]; // [B,S,D]

// ==================== helpers ====================
__device__ __forceinline__ uint32_t f2tf(float x) {
    uint32_t r;
    asm("cvt.rna.tf32.f32 %0, %1;" : "=r"(r) : "f"(x));
    return r;
}
// D = A(16x8, row) @ B(8x8, col) + D, tf32 inputs, f32 accum
__device__ __forceinline__ void mma8(float* c, const uint32_t* a,
                                     uint32_t b0, uint32_t b1) {
    asm volatile(
        "mma.sync.aligned.m16n8k8.row.col.f32.tf32.tf32.f32 "
        "{%0,%1,%2,%3}, {%4,%5,%6,%7}, {%8,%9}, {%0,%1,%2,%3};"
        : "+f"(c[0]), "+f"(c[1]), "+f"(c[2]), "+f"(c[3])
        : "r"(a[0]), "r"(a[1]), "r"(a[2]), "r"(a[3]), "r"(b0), "r"(b1));
}
__device__ __forceinline__ uint32_t smem_u32(const void* p) {
    uint32_t a;
    asm("{ .reg .u64 t; cvta.to.shared.u64 t, %1; cvt.u32.u64 %0, t; }" : "=r"(a) : "l"(p));
    return a;
}
__device__ __forceinline__ void cp16(uint32_t dst, const void* src) {
    asm volatile("cp.async.ca.shared.global [%0], [%1], 16;" :: "r"(dst), "l"(src) : "memory");
}
#define CP_COMMIT() asm volatile("cp.async.commit_group;" ::: "memory")
#define CP_WAIT0()  asm volatile("cp.async.wait_group 0;" ::: "memory")

// ==================== tf32 mma.sync GEMM: C = X @ W^T + bias ====================
// mode 0: C[m*768+n] plain fp32.
// mode 1: split-head scatter to [B,H,S,HD], value = tf32-rounded (acc+bias)*scale.
#define TBK 32
#define APITCH 36
#define STAGE_WORDS (128 * APITCH)                 // 4608 words
#define GEMM_SMEM (4 * STAGE_WORDS * 4)            // 73728 B

__global__ __launch_bounds__(256)
void mma_gemm_kernel(const float* __restrict__ A, const float* __restrict__ W,
                     const float* __restrict__ bias, float* __restrict__ C,
                     int mode, float scale)
{
    extern __shared__ uint32_t sm[];
    uint32_t* AsBase = sm;                       // [2][STAGE_WORDS]
    uint32_t* BsBase = sm + 2 * STAGE_WORDS;     // [2][STAGE_WORDS]

    const int tid  = threadIdx.x;
    const int lane = tid & 31, wid = tid >> 5;
    const int g = lane >> 2, tig = lane & 3;
    const int wm = wid >> 2, wn = wid & 3;       // 2 x 4 warp grid
    const int bm = blockIdx.y * 128, bn = blockIdx.x * 128;

    const int lr = tid >> 3;                     // 0..31
    const int lc = (tid & 7) * 4;                // 0,4,...,28
    const float* Ap = A + (size_t)(bm + lr) * DMODEL + lc;
    const float* Wp = W + (size_t)(bn + lr) * DMODEL + lc;

    float acc[4][4][4];
    #pragma unroll
    for (int i = 0; i < 4; i++)
        #pragma unroll
        for (int j = 0; j < 4; j++)
            #pragma unroll
            for (int t = 0; t < 4; t++) acc[i][j][t] = 0.f;

    float4 ra[4], rb[4];
    #pragma unroll
    for (int i = 0; i < 4; i++) {
        ra[i] = *(const float4*)(Ap + (size_t)i * 32 * DMODEL);
        rb[i] = *(const float4*)(Wp + (size_t)i * 32 * DMODEL);
    }
    #pragma unroll
    for (int i = 0; i < 4; i++) {
        const uint32_t idx = (uint32_t)(lr + 32 * i) * APITCH + lc;
        *(uint4*)&AsBase[idx] = make_uint4(f2tf(ra[i].x), f2tf(ra[i].y), f2tf(ra[i].z), f2tf(ra[i].w));
        *(uint4*)&BsBase[idx] = make_uint4(f2tf(rb[i].x), f2tf(rb[i].y), f2tf(rb[i].z), f2tf(rb[i].w));
    }
    __syncthreads();

    const int KT = DMODEL / TBK;                 // 24
    for (int kt = 0; kt < KT; kt++) {
        const int s = kt & 1;
        const uint32_t* Sa = AsBase + s * STAGE_WORDS;
        const uint32_t* Sb = BsBase + s * STAGE_WORDS;

        if (kt + 1 < KT) {
            const float* ap = Ap + (size_t)(kt + 1) * TBK;
            const float* wp = Wp + (size_t)(kt + 1) * TBK;
            #pragma unroll
            for (int i = 0; i < 4; i++) {
                ra[i] = *(const float4*)(ap + (size_t)i * 32 * DMODEL);
                rb[i] = *(const float4*)(wp + (size_t)i * 32 * DMODEL);
            }
        }

        #pragma unroll
        for (int kk = 0; kk < 4; kk++) {
            const int k0 = kk * 8;
            uint32_t af[4][4];
            #pragma unroll
            for (int mf = 0; mf < 4; mf++) {
                const uint32_t* bp = Sa + (uint32_t)(wm * 64 + mf * 16) * APITCH + k0;
                af[mf][0] = bp[(uint32_t)g * APITCH + tig];
                af[mf][1] = bp[(uint32_t)(g + 8) * APITCH + tig];
                af[mf][2] = bp[(uint32_t)g * APITCH + tig + 4];
                af[mf][3] = bp[(uint32_t)(g + 8) * APITCH + tig + 4];
            }
            uint32_t bf[4][2];
            #pragma unroll
            for (int nf = 0; nf < 4; nf++) {
                const uint32_t* bp = Sb + (uint32_t)(wn * 32 + nf * 8 + g) * APITCH + k0;
                bf[nf][0] = bp[tig];
                bf[nf][1] = bp[tig + 4];
            }
            #pragma unroll
            for (int mf = 0; mf < 4; mf++)
                #pragma unroll
                for (int nf = 0; nf < 4; nf++)
                    mma8(acc[mf][nf], af[mf], bf[nf][0], bf[nf][1]);
        }

        if (kt + 1 < KT) {
            __syncthreads();
            const int s1 = s ^ 1;
            #pragma unroll
            for (int i = 0; i < 4; i++) {
                const uint32_t idx = (uint32_t)(lr + 32 * i) * APITCH + lc;
                *(uint4*)&AsBase[s1 * STAGE_WORDS + idx] =
                    make_uint4(f2tf(ra[i].x), f2tf(ra[i].y), f2tf(ra[i].z), f2tf(ra[i].w));
                *(uint4*)&BsBase[s1 * STAGE_WORDS + idx] =
                    make_uint4(f2tf(rb[i].x), f2tf(rb[i].y), f2tf(rb[i].z), f2tf(rb[i].w));
            }
            __syncthreads();
        }
    }

    // epilogue
    #pragma unroll
    for (int mf = 0; mf < 4; mf++) {
        const int r0 = bm + wm * 64 + mf * 16 + g;
        #pragma unroll
        for (int nf = 0; nf < 4; nf++) {
            const int c = bn + wn * 32 + nf * 8 + tig * 2;
            const float b0 = bias[c], b1 = bias[c + 1];
            if (mode == 0) {
                float2 v0 = make_float2(acc[mf][nf][0] + b0, acc[mf][nf][1] + b1);
                float2 v1 = make_float2(acc[mf][nf][2] + b0, acc[mf][nf][3] + b1);
                *(float2*)(C + (size_t)r0 * DMODEL + c) = v0;
                *(float2*)(C + (size_t)(r0 + 8) * DMODEL + c) = v1;
            } else {
                float2 v0 = make_float2(
                    __uint_as_float(f2tf((acc[mf][nf][0] + b0) * scale)),
                    __uint_as_float(f2tf((acc[mf][nf][1] + b1) * scale)));
                float2 v1 = make_float2(
                    __uint_as_float(f2tf((acc[mf][nf][2] + b0) * scale)),
                    __uint_as_float(f2tf((acc[mf][nf][3] + b1) * scale)));
                const int h = c >> 6, hd = c & (HD - 1);
                const int bb0 = r0 >> 12, s0r = r0 & (SLEN - 1);
                *(float2*)(C + (((size_t)(bb0 * NH + h)) * SLEN + s0r) * HD + hd) = v0;
                const int r1 = r0 + 8;
                const int bb1 = r1 >> 12, s1r = r1 & (SLEN - 1);
                *(float2*)(C + (((size_t)(bb1 * NH + h)) * SLEN + s1r) * HD + hd) = v1;
            }
        }
    }
}

// ==================== flash attention with mma.sync (tf32) ====================
// Block: 128 thr (4 warps). 128 q-rows/block, 32 q-rows/warp, 64-key tiles.
// Inputs are pre-rounded tf32 bit patterns (Q also pre-scaled by 1/8).
// K tiles: row-major pitch 68 (banks 4g+tig: conflict-free B-frag loads).
// V tiles: row-major pitch 72 (banks 8tig+g: conflict-free B-frag loads).
#define QP 68
#define KP 68
#define VP 72
#define QS_OFF 0
#define KS_OFF (128 * QP)                  // 8704
#define KS_SZ  (64 * KP)                   // 4352
#define VS_OFF (KS_OFF + 2 * KS_SZ)        // 17408
#define VS_SZ  (64 * VP)                   // 4608
#define ATT_SMEM_BYTES ((VS_OFF + 2 * VS_SZ) * 4)   // 106496

__global__ __launch_bounds__(128)
void attn_mma_kernel(const float* __restrict__ Qh, const float* __restrict__ Kh,
                     const float* __restrict__ Vh, float* __restrict__ feats)
{
    extern __shared__ uint32_t sm[];
    const uint32_t sb = smem_u32(sm);
    const int tid = threadIdx.x, lane = tid & 31, w = tid >> 5;
    const int g = lane >> 2, tig = lane & 3;
    const int bh = blockIdx.y;
    const int qt = gridDim.x - 1 - blockIdx.x;     // LPT: heavy tiles first
    const int q0 = qt * 128;
    const int b = bh / NH, h = bh % NH;
    const size_t base = (size_t)bh * SLEN * HD;
    const int m0 = w * 32;

    const int sr = tid >> 1;                // 0..63 staging row
    const int scb = (tid & 1) * 32;         // staging col offset (words)

    // ---- prologue: async-stage Q tile + K0/V0 ----
    {
        const float* qsrc = Qh + base + (size_t)(q0 + tid) * HD;
        const uint32_t qdst = sb + (QS_OFF + (uint32_t)tid * QP) * 4;
        #pragma unroll
        for (int i = 0; i < 16; i++) cp16(qdst + i * 16, qsrc + i * 4);

        const float* ksrc = Kh + base + (size_t)sr * HD + scb;
        const float* vsrc = Vh + base + (size_t)sr * HD + scb;
        const uint32_t kdst = sb + (KS_OFF + (uint32_t)sr * KP + scb) * 4;
        const uint32_t vdst = sb + (VS_OFF + (uint32_t)sr * VP + scb) * 4;
        #pragma unroll
        for (int i = 0; i < 8; i++) {
            cp16(kdst + i * 16, ksrc + i * 4);
            cp16(vdst + i * 16, vsrc + i * 4);
        }
        CP_COMMIT();
    }
    CP_WAIT0();
    __syncthreads();

    // Q fragments resident: 2 mf blocks x 8 kf
    uint32_t qa[2][8][4];
    #pragma unroll
    for (int mf = 0; mf < 2; mf++) {
        const uint32_t rbase = (uint32_t)(m0 + mf * 16);
        #pragma unroll
        for (int kf = 0; kf < 8; kf++) {
            qa[mf][kf][0] = sm[QS_OFF + (rbase + g) * QP + kf * 8 + tig];
            qa[mf][kf][1] = sm[QS_OFF + (rbase + g + 8) * QP + kf * 8 + tig];
            qa[mf][kf][2] = sm[QS_OFF + (rbase + g) * QP + kf * 8 + tig + 4];
            qa[mf][kf][3] = sm[QS_OFF + (rbase + g + 8) * QP + kf * 8 + tig + 4];
        }
    }

    float o[2][8][4];
    #pragma unroll
    for (int mf = 0; mf < 2; mf++)
        #pragma unroll
        for (int nf = 0; nf < 8; nf++)
            #pragma unroll
            for (int t = 0; t < 4; t++) o[mf][nf][t] = 0.f;
    float mr[2][2] = {{-INFINITY, -INFINITY}, {-INFINITY, -INFINITY}};
    float l[2][2] = {{0.f, 0.f}, {0.f, 0.f}};

    const int ntiles = 2 * qt + 2;
    for (int kt = 0; kt < ntiles; kt++) {
        const int k0 = kt * 64;
        const int cbuf = kt & 1;

        // ---- issue async staging for next tile ----
        if (kt + 1 < ntiles) {
            const int nk0 = k0 + 64;
            const int nbuf = cbuf ^ 1;
            const float* ksrc = Kh + base + (size_t)(nk0 + sr) * HD + scb;
            const float* vsrc = Vh + base + (size_t)(nk0 + sr) * HD + scb;
            const uint32_t kdst = sb + (KS_OFF + (uint32_t)nbuf * KS_SZ + (uint32_t)sr * KP + scb) * 4;
            const uint32_t vdst = sb + (VS_OFF + (uint32_t)nbuf * VS_SZ + (uint32_t)sr * VP + scb) * 4;
            #pragma unroll
            for (int i = 0; i < 8; i++) {
                cp16(kdst + i * 16, ksrc + i * 4);
                cp16(vdst + i * 16, vsrc + i * 4);
            }
            CP_COMMIT();
        }

        const uint32_t* Ksm = sm + KS_OFF + (uint32_t)cbuf * KS_SZ;
        const uint32_t* Vsm = sm + VS_OFF + (uint32_t)cbuf * VS_SZ;

        const bool active = (k0 <= q0 + m0 + 31);   // warp-uniform
        if (active) {
            // ---- S = Q @ K^T : 32 x 64 per warp ----
            float sacc[2][8][4];
            #pragma unroll
            for (int mf = 0; mf < 2; mf++)
                #pragma unroll
                for (int nf = 0; nf < 8; nf++)
                    #pragma unroll
                    for (int t = 0; t < 4; t++) sacc[mf][nf][t] = 0.f;
            #pragma unroll
            for (int kf = 0; kf < 8; kf++) {
                #pragma unroll
                for (int nf = 0; nf < 8; nf++) {
                    const uint32_t* bp = Ksm + (uint32_t)(nf * 8 + g) * KP + kf * 8;
                    const uint32_t b0 = bp[tig], b1 = bp[tig + 4];
                    mma8(sacc[0][nf], qa[0][kf], b0, b1);
                    mma8(sacc[1][nf], qa[1][kf], b0, b1);
                }
            }

            // ---- causal mask (only near diagonal) ----
            if (k0 + 63 > q0 + m0) {
                #pragma unroll
                for (int mf = 0; mf < 2; mf++) {
                    const int rA = q0 + m0 + mf * 16 + g;
                    const int rB = rA + 8;
                    #pragma unroll
                    for (int nf = 0; nf < 8; nf++) {
                        const int c0 = k0 + nf * 8 + tig * 2;
                        if (c0 > rA)     sacc[mf][nf][0] = -1e30f;
                        if (c0 + 1 > rA) sacc[mf][nf][1] = -1e30f;
                        if (c0 > rB)     sacc[mf][nf][2] = -1e30f;
                        if (c0 + 1 > rB) sacc[mf][nf][3] = -1e30f;
                    }
                }
            }

            // ---- online softmax per mf (rows g, g+8) ----
            #pragma unroll
            for (int mf = 0; mf < 2; mf++) {
                float tm0 = -1e30f, tm1 = -1e30f;
                #pragma unroll
                for (int nf = 0; nf < 8; nf++) {
                    tm0 = fmaxf(tm0, fmaxf(sacc[mf][nf][0], sacc[mf][nf][1]));
                    tm1 = fmaxf(tm1, fmaxf(sacc[mf][nf][2], sacc[mf][nf][3]));
                }
                tm0 = fmaxf(tm0, __shfl_xor_sync(0xffffffffu, tm0, 1));
                tm0 = fmaxf(tm0, __shfl_xor_sync(0xffffffffu, tm0, 2));
                tm1 = fmaxf(tm1, __shfl_xor_sync(0xffffffffu, tm1, 1));
                tm1 = fmaxf(tm1, __shfl_xor_sync(0xffffffffu, tm1, 2));
                const float mn0 = fmaxf(mr[mf][0], tm0), mn1 = fmaxf(mr[mf][1], tm1);
                const float al0 = __expf(mr[mf][0] - mn0), al1 = __expf(mr[mf][1] - mn1);
                mr[mf][0] = mn0; mr[mf][1] = mn1;
                l[mf][0] *= al0; l[mf][1] *= al1;
                #pragma unroll
                for (int nf = 0; nf < 8; nf++) {
                    o[mf][nf][0] *= al0; o[mf][nf][1] *= al0;
                    o[mf][nf][2] *= al1; o[mf][nf][3] *= al1;
                }
                #pragma unroll
                for (int nf = 0; nf < 8; nf++) {
                    const float e0 = __expf(sacc[mf][nf][0] - mn0);
                    const float e1 = __expf(sacc[mf][nf][1] - mn0);
                    const float e2 = __expf(sacc[mf][nf][2] - mn1);
                    const float e3 = __expf(sacc[mf][nf][3] - mn1);
                    l[mf][0] += e0 + e1; l[mf][1] += e2 + e3;
                    sacc[mf][nf][0] = e0; sacc[mf][nf][1] = e1;
                    sacc[mf][nf][2] = e2; sacc[mf][nf][3] = e3;
                }
            }

            // ---- O += P @ V ----
            const int sl0 = (lane & ~3) | (tig >> 1);
            const int sl2 = sl0 + 2;
            const bool odd = (tig & 1) != 0;
            #pragma unroll
            for (int kf = 0; kf < 8; kf++) {
                uint32_t pa[2][4];
                #pragma unroll
                for (int mf = 0; mf < 2; mf++) {
                    const float e0 = sacc[mf][kf][0], e1 = sacc[mf][kf][1];
                    const float e2 = sacc[mf][kf][2], e3 = sacc[mf][kf][3];
                    const float x00 = __shfl_sync(0xffffffffu, e0, sl0);
                    const float x10 = __shfl_sync(0xffffffffu, e1, sl0);
                    const float x02 = __shfl_sync(0xffffffffu, e0, sl2);
                    const float x12 = __shfl_sync(0xffffffffu, e1, sl2);
                    const float x20 = __shfl_sync(0xffffffffu, e2, sl0);
                    const float x30 = __shfl_sync(0xffffffffu, e3, sl0);
                    const float x22 = __shfl_sync(0xffffffffu, e2, sl2);
                    const float x32 = __shfl_sync(0xffffffffu, e3, sl2);
                    pa[mf][0] = f2tf(odd ? x10 : x00);
                    pa[mf][1] = f2tf(odd ? x30 : x20);
                    pa[mf][2] = f2tf(odd ? x12 : x02);
                    pa[mf][3] = f2tf(odd ? x32 : x22);
                }
                #pragma unroll
                for (int nf = 0; nf < 8; nf++) {
                    const uint32_t* bp = Vsm + (uint32_t)(kf * 8 + tig) * VP + nf * 8 + g;
                    const uint32_t b0 = bp[0], b1 = bp[4 * VP];
                    mma8(o[0][nf], pa[0], b0, b1);
                    mma8(o[1][nf], pa[1], b0, b1);
                }
            }
        }

        if (kt + 1 < ntiles) CP_WAIT0();
        __syncthreads();
    }

    // ---- finalize ----
    #pragma unroll
    for (int mf = 0; mf < 2; mf++) {
        float l0 = l[mf][0], l1 = l[mf][1];
        l0 += __shfl_xor_sync(0xffffffffu, l0, 1);
        l0 += __shfl_xor_sync(0xffffffffu, l0, 2);
        l1 += __shfl_xor_sync(0xffffffffu, l1, 1);
        l1 += __shfl_xor_sync(0xffffffffu, l1, 2);
        const float i0 = 1.f / l0, i1 = 1.f / l1;
        const int r0 = q0 + m0 + mf * 16 + g;
        #pragma unroll
        for (int nf = 0; nf < 8; nf++) {
            const int col = h * HD + nf * 8 + tig * 2;
            *(float2*)(feats + ((size_t)(b * SLEN + r0)) * DMODEL + col) =
                make_float2(o[mf][nf][0] * i0, o[mf][nf][1] * i0);
            *(float2*)(feats + ((size_t)(b * SLEN + r0 + 8)) * DMODEL + col) =
                make_float2(o[mf][nf][2] * i1, o[mf][nf][3] * i1);
        }
    }
}

// ==================== launch ====================
extern "C" void kernel_launch(void* const* d_in, const int* in_sizes, int n_in,
                              void* d_out, int out_size)
{
    const float* q  = (const float*)d_in[0];
    const float* k  = (const float*)d_in[1];
    const float* v  = (const float*)d_in[2];
    // d_in[3] = mask (always causal triu(k=1); handled analytically)
    const float* Wq = (const float*)d_in[4];
    const float* bq = (const float*)d_in[5];
    const float* Wk = (const float*)d_in[6];
    const float* bk = (const float*)d_in[7];
    const float* Wv = (const float*)d_in[8];
    const float* bv = (const float*)d_in[9];
    const float* Wo = (const float*)d_in[10];
    const float* bo = (const float*)d_in[11];

    float *qh, *kh, *vh, *feats;
    cudaGetSymbolAddress((void**)&qh, g_qh);
    cudaGetSymbolAddress((void**)&kh, g_kh);
    cudaGetSymbolAddress((void**)&vh, g_vh);
    cudaGetSymbolAddress((void**)&feats, g_feats);

    cudaFuncSetAttribute(mma_gemm_kernel,
                         cudaFuncAttributeMaxDynamicSharedMemorySize, GEMM_SMEM);
    cudaFuncSetAttribute(attn_mma_kernel,
                         cudaFuncAttributeMaxDynamicSharedMemorySize, ATT_SMEM_BYTES);

    dim3 gg(DMODEL / 128, MROWS / 128);   // (6, 64)
    mma_gemm_kernel<<<gg, 256, GEMM_SMEM>>>(q, Wq, bq, qh, 1, 0.125f);
    mma_gemm_kernel<<<gg, 256, GEMM_SMEM>>>(k, Wk, bk, kh, 1, 1.0f);
    mma_gemm_kernel<<<gg, 256, GEMM_SMEM>>>(v, Wv, bv, vh, 1, 1.0f);

    attn_mma_kernel<<<dim3(SLEN / 128, BATCH * NH), 128, ATT_SMEM_BYTES>>>(qh, kh, vh, feats);

    mma_gemm_kernel<<<gg, 256, GEMM_SMEM>>>(feats, Wo, bo, (float*)d_out, 0, 1.0f);
}

// round 8
// speedup vs baseline: 1.0716x; 1.0716x over previous
#include <cuda_runtime.h>
#include <math.h>
#include <stdint.h>

// Problem constants
#define BATCH 2
#define SLEN  4096
#define DMODEL 768
#define NH    12
#define HD    64
#define MROWS (BATCH * SLEN)        // 8192

// ---------------- scratch (device globals; allocation-free) ----------------
__device__ float g_qh[BATCH * NH * SLEN * HD];   // [B,H,S,HD] (tf32-rounded, pre-scaled)
__device__ float g_kh[BATCH * NH * SLEN * HD];   // tf32-rounded
__device__ float g_vh[BATCH * NH * SLEN * HD];   // tf32-rounded
__device__ float g_feats[BATCH * SLEN * DMODEL]; // [B,S,D]

// ==================== helpers ====================
__device__ __forceinline__ uint32_t f2tf(float x) {
    uint32_t r;
    asm("cvt.rna.tf32.f32 %0, %1;" : "=r"(r) : "f"(x));
    return r;
}
// D = A(16x8, row) @ B(8x8, col) + D, tf32 inputs, f32 accum
__device__ __forceinline__ void mma8(float* c, const uint32_t* a,
                                     uint32_t b0, uint32_t b1) {
    asm volatile(
        "mma.sync.aligned.m16n8k8.row.col.f32.tf32.tf32.f32 "
        "{%0,%1,%2,%3}, {%4,%5,%6,%7}, {%8,%9}, {%0,%1,%2,%3};"
        : "+f"(c[0]), "+f"(c[1]), "+f"(c[2]), "+f"(c[3])
        : "r"(a[0]), "r"(a[1]), "r"(a[2]), "r"(a[3]), "r"(b0), "r"(b1));
}

// ==================== tf32 mma.sync GEMM: C = X @ W^T + bias ====================
// mode 0: C[m*768+n] plain fp32.
// mode 1: split-head scatter to [B,H,S,HD], value = tf32-rounded (acc+bias)*scale.
#define TBK 32
#define APITCH 36
#define STAGE_WORDS (128 * APITCH)                 // 4608 words
#define GEMM_SMEM (4 * STAGE_WORDS * 4)            // 73728 B

__global__ __launch_bounds__(256)
void mma_gemm_kernel(const float* __restrict__ A, const float* __restrict__ W,
                     const float* __restrict__ bias, float* __restrict__ C,
                     int mode, float scale)
{
    extern __shared__ uint32_t sm[];
    uint32_t* AsBase = sm;                       // [2][STAGE_WORDS]
    uint32_t* BsBase = sm + 2 * STAGE_WORDS;     // [2][STAGE_WORDS]

    const int tid  = threadIdx.x;
    const int lane = tid & 31, wid = tid >> 5;
    const int g = lane >> 2, tig = lane & 3;
    const int wm = wid >> 2, wn = wid & 3;       // 2 x 4 warp grid
    const int bm = blockIdx.y * 128, bn = blockIdx.x * 128;

    const int lr = tid >> 3;                     // 0..31
    const int lc = (tid & 7) * 4;                // 0,4,...,28
    const float* Ap = A + (size_t)(bm + lr) * DMODEL + lc;
    const float* Wp = W + (size_t)(bn + lr) * DMODEL + lc;

    float acc[4][4][4];
    #pragma unroll
    for (int i = 0; i < 4; i++)
        #pragma unroll
        for (int j = 0; j < 4; j++)
            #pragma unroll
            for (int t = 0; t < 4; t++) acc[i][j][t] = 0.f;

    float4 ra[4], rb[4];
    #pragma unroll
    for (int i = 0; i < 4; i++) {
        ra[i] = *(const float4*)(Ap + (size_t)i * 32 * DMODEL);
        rb[i] = *(const float4*)(Wp + (size_t)i * 32 * DMODEL);
    }
    #pragma unroll
    for (int i = 0; i < 4; i++) {
        const uint32_t idx = (uint32_t)(lr + 32 * i) * APITCH + lc;
        *(uint4*)&AsBase[idx] = make_uint4(f2tf(ra[i].x), f2tf(ra[i].y), f2tf(ra[i].z), f2tf(ra[i].w));
        *(uint4*)&BsBase[idx] = make_uint4(f2tf(rb[i].x), f2tf(rb[i].y), f2tf(rb[i].z), f2tf(rb[i].w));
    }
    __syncthreads();

    const int KT = DMODEL / TBK;                 // 24
    for (int kt = 0; kt < KT; kt++) {
        const int s = kt & 1;
        const uint32_t* Sa = AsBase + s * STAGE_WORDS;
        const uint32_t* Sb = BsBase + s * STAGE_WORDS;

        if (kt + 1 < KT) {
            const float* ap = Ap + (size_t)(kt + 1) * TBK;
            const float* wp = Wp + (size_t)(kt + 1) * TBK;
            #pragma unroll
            for (int i = 0; i < 4; i++) {
                ra[i] = *(const float4*)(ap + (size_t)i * 32 * DMODEL);
                rb[i] = *(const float4*)(wp + (size_t)i * 32 * DMODEL);
            }
        }

        #pragma unroll
        for (int kk = 0; kk < 4; kk++) {
            const int k0 = kk * 8;
            uint32_t af[4][4];
            #pragma unroll
            for (int mf = 0; mf < 4; mf++) {
                const uint32_t* bp = Sa + (uint32_t)(wm * 64 + mf * 16) * APITCH + k0;
                af[mf][0] = bp[(uint32_t)g * APITCH + tig];
                af[mf][1] = bp[(uint32_t)(g + 8) * APITCH + tig];
                af[mf][2] = bp[(uint32_t)g * APITCH + tig + 4];
                af[mf][3] = bp[(uint32_t)(g + 8) * APITCH + tig + 4];
            }
            uint32_t bf[4][2];
            #pragma unroll
            for (int nf = 0; nf < 4; nf++) {
                const uint32_t* bp = Sb + (uint32_t)(wn * 32 + nf * 8 + g) * APITCH + k0;
                bf[nf][0] = bp[tig];
                bf[nf][1] = bp[tig + 4];
            }
            #pragma unroll
            for (int mf = 0; mf < 4; mf++)
                #pragma unroll
                for (int nf = 0; nf < 4; nf++)
                    mma8(acc[mf][nf], af[mf], bf[nf][0], bf[nf][1]);
        }

        if (kt + 1 < KT) {
            __syncthreads();
            const int s1 = s ^ 1;
            #pragma unroll
            for (int i = 0; i < 4; i++) {
                const uint32_t idx = (uint32_t)(lr + 32 * i) * APITCH + lc;
                *(uint4*)&AsBase[s1 * STAGE_WORDS + idx] =
                    make_uint4(f2tf(ra[i].x), f2tf(ra[i].y), f2tf(ra[i].z), f2tf(ra[i].w));
                *(uint4*)&BsBase[s1 * STAGE_WORDS + idx] =
                    make_uint4(f2tf(rb[i].x), f2tf(rb[i].y), f2tf(rb[i].z), f2tf(rb[i].w));
            }
            __syncthreads();
        }
    }

    // epilogue
    #pragma unroll
    for (int mf = 0; mf < 4; mf++) {
        const int r0 = bm + wm * 64 + mf * 16 + g;
        #pragma unroll
        for (int nf = 0; nf < 4; nf++) {
            const int c = bn + wn * 32 + nf * 8 + tig * 2;
            const float b0 = bias[c], b1 = bias[c + 1];
            if (mode == 0) {
                float2 v0 = make_float2(acc[mf][nf][0] + b0, acc[mf][nf][1] + b1);
                float2 v1 = make_float2(acc[mf][nf][2] + b0, acc[mf][nf][3] + b1);
                *(float2*)(C + (size_t)r0 * DMODEL + c) = v0;
                *(float2*)(C + (size_t)(r0 + 8) * DMODEL + c) = v1;
            } else {
                float2 v0 = make_float2(
                    __uint_as_float(f2tf((acc[mf][nf][0] + b0) * scale)),
                    __uint_as_float(f2tf((acc[mf][nf][1] + b1) * scale)));
                float2 v1 = make_float2(
                    __uint_as_float(f2tf((acc[mf][nf][2] + b0) * scale)),
                    __uint_as_float(f2tf((acc[mf][nf][3] + b1) * scale)));
                const int h = c >> 6, hd = c & (HD - 1);
                const int bb0 = r0 >> 12, s0r = r0 & (SLEN - 1);
                *(float2*)(C + (((size_t)(bb0 * NH + h)) * SLEN + s0r) * HD + hd) = v0;
                const int r1 = r0 + 8;
                const int bb1 = r1 >> 12, s1r = r1 & (SLEN - 1);
                *(float2*)(C + (((size_t)(bb1 * NH + h)) * SLEN + s1r) * HD + hd) = v1;
            }
        }
    }
}

// ==================== flash attention with mma.sync (tf32) ====================
// Block: 128 thr (4 warps). 128 q-rows/block, 32 q-rows/warp, 64-key tiles.
// Inputs are pre-rounded tf32 bit patterns (Q also pre-scaled by 1/8).
// K: row-major pitch 68 (B-frag banks 4g+tig: conflict-free).
// V: row-major pitch 72 (B-frag banks 8(tig+nf)+g: conflict-free).
#define QP 68
#define KP 68
#define VP 72
#define QS_OFF 0
#define KS_OFF (128 * QP)                  // 8704
#define VS_OFF (KS_OFF + 64 * KP)          // 13056
#define ATT_SMEM_BYTES ((VS_OFF + 64 * VP) * 4)   // 70656

__global__ __launch_bounds__(128)
void attn_mma_kernel(const float* __restrict__ Qh, const float* __restrict__ Kh,
                     const float* __restrict__ Vh, float* __restrict__ feats)
{
    extern __shared__ uint32_t sm[];
    const int tid = threadIdx.x, lane = tid & 31, w = tid >> 5;
    const int g = lane >> 2, tig = lane & 3;
    const int bh = blockIdx.y;
    const int qt = gridDim.x - 1 - blockIdx.x;     // LPT: heavy tiles first
    const int q0 = qt * 128;
    const int b = bh / NH, h = bh % NH;
    const size_t base = (size_t)bh * SLEN * HD;
    const int m0 = w * 32;

    const int sr = tid >> 1;                // 0..63 staging row
    const int scb = (tid & 1) * 32;         // staging col offset (words)

    // ---- stage Q tile (128 x 64): straight copy (already tf32+scaled) ----
    {
        const float4* src = (const float4*)(Qh + base + (size_t)(q0 + tid) * HD);
        float* dst = (float*)sm + QS_OFF + (uint32_t)tid * QP;
        #pragma unroll
        for (int i = 0; i < 16; i++) *(float4*)(dst + i * 4) = src[i];
    }
    __syncthreads();

    // Q fragments resident: 2 mf blocks x 8 kf
    uint32_t qa[2][8][4];
    #pragma unroll
    for (int mf = 0; mf < 2; mf++) {
        const uint32_t rbase = (uint32_t)(m0 + mf * 16);
        #pragma unroll
        for (int kf = 0; kf < 8; kf++) {
            qa[mf][kf][0] = sm[QS_OFF + (rbase + g) * QP + kf * 8 + tig];
            qa[mf][kf][1] = sm[QS_OFF + (rbase + g + 8) * QP + kf * 8 + tig];
            qa[mf][kf][2] = sm[QS_OFF + (rbase + g) * QP + kf * 8 + tig + 4];
            qa[mf][kf][3] = sm[QS_OFF + (rbase + g + 8) * QP + kf * 8 + tig + 4];
        }
    }

    float o[2][8][4];
    #pragma unroll
    for (int mf = 0; mf < 2; mf++)
        #pragma unroll
        for (int nf = 0; nf < 8; nf++)
            #pragma unroll
            for (int t = 0; t < 4; t++) o[mf][nf][t] = 0.f;
    float mr[2][2] = {{-INFINITY, -INFINITY}, {-INFINITY, -INFINITY}};
    float l[2][2] = {{0.f, 0.f}, {0.f, 0.f}};

    const int ntiles = 2 * qt + 2;
    for (int kt = 0; kt < ntiles; kt++) {
        const int k0 = kt * 64;
        // ---- stage K tile (64 x 64) + V tile (64 x 64): straight copies ----
        {
            const float4* ksrc = (const float4*)(Kh + base + (size_t)(k0 + sr) * HD + scb);
            const float4* vsrc = (const float4*)(Vh + base + (size_t)(k0 + sr) * HD + scb);
            float* kdst = (float*)sm + KS_OFF + (uint32_t)sr * KP + scb;
            float* vdst = (float*)sm + VS_OFF + (uint32_t)sr * VP + scb;
            #pragma unroll
            for (int i = 0; i < 8; i++) {
                *(float4*)(kdst + i * 4) = ksrc[i];
                *(float4*)(vdst + i * 4) = vsrc[i];
            }
        }
        __syncthreads();

        const uint32_t* Ksm = sm + KS_OFF;
        const uint32_t* Vsm = sm + VS_OFF;

        const bool active = (k0 <= q0 + m0 + 31);   // warp-uniform
        if (active) {
            // ---- S = Q @ K^T : 32 x 64 per warp ----
            float sacc[2][8][4];
            #pragma unroll
            for (int mf = 0; mf < 2; mf++)
                #pragma unroll
                for (int nf = 0; nf < 8; nf++)
                    #pragma unroll
                    for (int t = 0; t < 4; t++) sacc[mf][nf][t] = 0.f;
            #pragma unroll
            for (int kf = 0; kf < 8; kf++) {
                #pragma unroll
                for (int nf = 0; nf < 8; nf++) {
                    const uint32_t* bp = Ksm + (uint32_t)(nf * 8 + g) * KP + kf * 8;
                    const uint32_t b0 = bp[tig], b1 = bp[tig + 4];
                    mma8(sacc[0][nf], qa[0][kf], b0, b1);
                    mma8(sacc[1][nf], qa[1][kf], b0, b1);
                }
            }

            // ---- causal mask (only near diagonal) ----
            if (k0 + 63 > q0 + m0) {
                #pragma unroll
                for (int mf = 0; mf < 2; mf++) {
                    const int rA = q0 + m0 + mf * 16 + g;
                    const int rB = rA + 8;
                    #pragma unroll
                    for (int nf = 0; nf < 8; nf++) {
                        const int c0 = k0 + nf * 8 + tig * 2;
                        if (c0 > rA)     sacc[mf][nf][0] = -1e30f;
                        if (c0 + 1 > rA) sacc[mf][nf][1] = -1e30f;
                        if (c0 > rB)     sacc[mf][nf][2] = -1e30f;
                        if (c0 + 1 > rB) sacc[mf][nf][3] = -1e30f;
                    }
                }
            }

            // ---- online softmax per mf (rows g, g+8) ----
            #pragma unroll
            for (int mf = 0; mf < 2; mf++) {
                float tm0 = -1e30f, tm1 = -1e30f;
                #pragma unroll
                for (int nf = 0; nf < 8; nf++) {
                    tm0 = fmaxf(tm0, fmaxf(sacc[mf][nf][0], sacc[mf][nf][1]));
                    tm1 = fmaxf(tm1, fmaxf(sacc[mf][nf][2], sacc[mf][nf][3]));
                }
                tm0 = fmaxf(tm0, __shfl_xor_sync(0xffffffffu, tm0, 1));
                tm0 = fmaxf(tm0, __shfl_xor_sync(0xffffffffu, tm0, 2));
                tm1 = fmaxf(tm1, __shfl_xor_sync(0xffffffffu, tm1, 1));
                tm1 = fmaxf(tm1, __shfl_xor_sync(0xffffffffu, tm1, 2));
                const float mn0 = fmaxf(mr[mf][0], tm0), mn1 = fmaxf(mr[mf][1], tm1);
                const float al0 = __expf(mr[mf][0] - mn0), al1 = __expf(mr[mf][1] - mn1);
                mr[mf][0] = mn0; mr[mf][1] = mn1;
                l[mf][0] *= al0; l[mf][1] *= al1;
                #pragma unroll
                for (int nf = 0; nf < 8; nf++) {
                    o[mf][nf][0] *= al0; o[mf][nf][1] *= al0;
                    o[mf][nf][2] *= al1; o[mf][nf][3] *= al1;
                }
                #pragma unroll
                for (int nf = 0; nf < 8; nf++) {
                    const float e0 = __expf(sacc[mf][nf][0] - mn0);
                    const float e1 = __expf(sacc[mf][nf][1] - mn0);
                    const float e2 = __expf(sacc[mf][nf][2] - mn1);
                    const float e3 = __expf(sacc[mf][nf][3] - mn1);
                    l[mf][0] += e0 + e1; l[mf][1] += e2 + e3;
                    sacc[mf][nf][0] = e0; sacc[mf][nf][1] = e1;
                    sacc[mf][nf][2] = e2; sacc[mf][nf][3] = e3;
                }
            }

            // ---- O += P @ V ----
            const int sl0 = (lane & ~3) | (tig >> 1);
            const int sl2 = sl0 + 2;
            const bool odd = (tig & 1) != 0;
            #pragma unroll
            for (int kf = 0; kf < 8; kf++) {
                uint32_t pa[2][4];
                #pragma unroll
                for (int mf = 0; mf < 2; mf++) {
                    const float e0 = sacc[mf][kf][0], e1 = sacc[mf][kf][1];
                    const float e2 = sacc[mf][kf][2], e3 = sacc[mf][kf][3];
                    const float x00 = __shfl_sync(0xffffffffu, e0, sl0);
                    const float x10 = __shfl_sync(0xffffffffu, e1, sl0);
                    const float x02 = __shfl_sync(0xffffffffu, e0, sl2);
                    const float x12 = __shfl_sync(0xffffffffu, e1, sl2);
                    const float x20 = __shfl_sync(0xffffffffu, e2, sl0);
                    const float x30 = __shfl_sync(0xffffffffu, e3, sl0);
                    const float x22 = __shfl_sync(0xffffffffu, e2, sl2);
                    const float x32 = __shfl_sync(0xffffffffu, e3, sl2);
                    pa[mf][0] = f2tf(odd ? x10 : x00);
                    pa[mf][1] = f2tf(odd ? x30 : x20);
                    pa[mf][2] = f2tf(odd ? x12 : x02);
                    pa[mf][3] = f2tf(odd ? x32 : x22);
                }
                #pragma unroll
                for (int nf = 0; nf < 8; nf++) {
                    const uint32_t* bp = Vsm + (uint32_t)(kf * 8 + tig) * VP + nf * 8 + g;
                    const uint32_t b0 = bp[0], b1 = bp[4 * VP];
                    mma8(o[0][nf], pa[0], b0, b1);
                    mma8(o[1][nf], pa[1], b0, b1);
                }
            }
        }
        __syncthreads();
    }

    // ---- finalize ----
    #pragma unroll
    for (int mf = 0; mf < 2; mf++) {
        float l0 = l[mf][0], l1 = l[mf][1];
        l0 += __shfl_xor_sync(0xffffffffu, l0, 1);
        l0 += __shfl_xor_sync(0xffffffffu, l0, 2);
        l1 += __shfl_xor_sync(0xffffffffu, l1, 1);
        l1 += __shfl_xor_sync(0xffffffffu, l1, 2);
        const float i0 = 1.f / l0, i1 = 1.f / l1;
        const int r0 = q0 + m0 + mf * 16 + g;
        #pragma unroll
        for (int nf = 0; nf < 8; nf++) {
            const int col = h * HD + nf * 8 + tig * 2;
            *(float2*)(feats + ((size_t)(b * SLEN + r0)) * DMODEL + col) =
                make_float2(o[mf][nf][0] * i0, o[mf][nf][1] * i0);
            *(float2*)(feats + ((size_t)(b * SLEN + r0 + 8)) * DMODEL + col) =
                make_float2(o[mf][nf][2] * i1, o[mf][nf][3] * i1);
        }
    }
}

// ==================== launch ====================
extern "C" void kernel_launch(void* const* d_in, const int* in_sizes, int n_in,
                              void* d_out, int out_size)
{
    const float* q  = (const float*)d_in[0];
    const float* k  = (const float*)d_in[1];
    const float* v  = (const float*)d_in[2];
    // d_in[3] = mask (always causal triu(k=1); handled analytically)
    const float* Wq = (const float*)d_in[4];
    const float* bq = (const float*)d_in[5];
    const float* Wk = (const float*)d_in[6];
    const float* bk = (const float*)d_in[7];
    const float* Wv = (const float*)d_in[8];
    const float* bv = (const float*)d_in[9];
    const float* Wo = (const float*)d_in[10];
    const float* bo = (const float*)d_in[11];

    float *qh, *kh, *vh, *feats;
    cudaGetSymbolAddress((void**)&qh, g_qh);
    cudaGetSymbolAddress((void**)&kh, g_kh);
    cudaGetSymbolAddress((void**)&vh, g_vh);
    cudaGetSymbolAddress((void**)&feats, g_feats);

    cudaFuncSetAttribute(mma_gemm_kernel,
                         cudaFuncAttributeMaxDynamicSharedMemorySize, GEMM_SMEM);
    cudaFuncSetAttribute(attn_mma_kernel,
                         cudaFuncAttributeMaxDynamicSharedMemorySize, ATT_SMEM_BYTES);

    dim3 gg(DMODEL / 128, MROWS / 128);   // (6, 64)
    mma_gemm_kernel<<<gg, 256, GEMM_SMEM>>>(q, Wq, bq, qh, 1, 0.125f);
    mma_gemm_kernel<<<gg, 256, GEMM_SMEM>>>(k, Wk, bk, kh, 1, 1.0f);
    mma_gemm_kernel<<<gg, 256, GEMM_SMEM>>>(v, Wv, bv, vh, 1, 1.0f);

    attn_mma_kernel<<<dim3(SLEN / 128, BATCH * NH), 128, ATT_SMEM_BYTES>>>(qh, kh, vh, feats);

    mma_gemm_kernel<<<gg, 256, GEMM_SMEM>>>(feats, Wo, bo, (float*)d_out, 0, 1.0f);
}

// round 11
// speedup vs baseline: 1.3825x; 1.2901x over previous
#include <cuda_runtime.h>
#include <cuda_fp16.h>
#include <math.h>
#include <stdint.h>

// Problem constants
#define BATCH 2
#define SLEN  4096
#define DMODEL 768
#define NH    12
#define HD    64
#define MROWS (BATCH * SLEN)        // 8192

// ---------------- scratch (device globals; allocation-free) ----------------
__device__ float g_qh[BATCH * NH * SLEN * HD];   // [B,H,S,HD] tf32-rounded, pre-scaled by log2e/8
__device__ float g_kh[BATCH * NH * SLEN * HD];   // [B,H,S,HD] tf32-rounded
__device__ __half g_vt[BATCH * NH * HD * SLEN];  // [B,H,HD,S] fp16 (transposed)
__device__ float g_feats[BATCH * SLEN * DMODEL]; // [B,S,D]

// ==================== helpers ====================
__device__ __forceinline__ uint32_t f2tf(float x) {
    uint32_t r;
    asm("cvt.rna.tf32.f32 %0, %1;" : "=r"(r) : "f"(x));
    return r;
}
__device__ __forceinline__ float ex2(float x) {
    float r;
    asm("ex2.approx.f32 %0, %1;" : "=f"(r) : "f"(x));
    return r;
}
// pack two f32 into f16x2: lo <- a, hi <- b
__device__ __forceinline__ uint32_t pack_h(float a, float b) {
    uint32_t r;
    asm("cvt.rn.f16x2.f32 %0, %1, %2;" : "=r"(r) : "f"(b), "f"(a));
    return r;
}
// tf32: D(16x8) = A @ B + D
__device__ __forceinline__ void mma8(float* c, const uint32_t* a,
                                     uint32_t b0, uint32_t b1) {
    asm volatile(
        "mma.sync.aligned.m16n8k8.row.col.f32.tf32.tf32.f32 "
        "{%0,%1,%2,%3}, {%4,%5,%6,%7}, {%8,%9}, {%0,%1,%2,%3};"
        : "+f"(c[0]), "+f"(c[1]), "+f"(c[2]), "+f"(c[3])
        : "r"(a[0]), "r"(a[1]), "r"(a[2]), "r"(a[3]), "r"(b0), "r"(b1));
}
// fp16: D(16x8) = A(16x16) @ B(16x8) + D, f32 accum
__device__ __forceinline__ void mma16h(float* c, const uint32_t* a,
                                       uint32_t b0, uint32_t b1) {
    asm volatile(
        "mma.sync.aligned.m16n8k16.row.col.f32.f16.f16.f32 "
        "{%0,%1,%2,%3}, {%4,%5,%6,%7}, {%8,%9}, {%0,%1,%2,%3};"
        : "+f"(c[0]), "+f"(c[1]), "+f"(c[2]), "+f"(c[3])
        : "r"(a[0]), "r"(a[1]), "r"(a[2]), "r"(a[3]), "r"(b0), "r"(b1));
}

// ==================== tf32 mma.sync GEMM: C = X @ W^T + bias ====================
// mode 0: C[m*768+n] plain fp32.
// mode 1: split-head scatter to [B,H,S,HD], value = tf32-rounded (acc+bias)*scale.
// mode 2: fp16 transposed scatter to VT[B,H,HD,S].
#define TBK 32
#define APITCH 36
#define STAGE_WORDS (128 * APITCH)                 // 4608 words
#define GEMM_SMEM (4 * STAGE_WORDS * 4)            // 73728 B

__global__ __launch_bounds__(256)
void mma_gemm_kernel(const float* __restrict__ A, const float* __restrict__ W,
                     const float* __restrict__ bias, float* __restrict__ C,
                     __half* __restrict__ VT, int mode, float scale)
{
    extern __shared__ uint32_t sm[];
    uint32_t* AsBase = sm;                       // [2][STAGE_WORDS]
    uint32_t* BsBase = sm + 2 * STAGE_WORDS;     // [2][STAGE_WORDS]

    const int tid  = threadIdx.x;
    const int lane = tid & 31, wid = tid >> 5;
    const int g = lane >> 2, tig = lane & 3;
    const int wm = wid >> 2, wn = wid & 3;       // 2 x 4 warp grid
    const int bm = blockIdx.y * 128, bn = blockIdx.x * 128;

    const int lr = tid >> 3;                     // 0..31
    const int lc = (tid & 7) * 4;                // 0,4,...,28
    const float* Ap = A + (size_t)(bm + lr) * DMODEL + lc;
    const float* Wp = W + (size_t)(bn + lr) * DMODEL + lc;

    float acc[4][4][4];
    #pragma unroll
    for (int i = 0; i < 4; i++)
        #pragma unroll
        for (int j = 0; j < 4; j++)
            #pragma unroll
            for (int t = 0; t < 4; t++) acc[i][j][t] = 0.f;

    float4 ra[4], rb[4];
    #pragma unroll
    for (int i = 0; i < 4; i++) {
        ra[i] = *(const float4*)(Ap + (size_t)i * 32 * DMODEL);
        rb[i] = *(const float4*)(Wp + (size_t)i * 32 * DMODEL);
    }
    #pragma unroll
    for (int i = 0; i < 4; i++) {
        const uint32_t idx = (uint32_t)(lr + 32 * i) * APITCH + lc;
        *(uint4*)&AsBase[idx] = make_uint4(f2tf(ra[i].x), f2tf(ra[i].y), f2tf(ra[i].z), f2tf(ra[i].w));
        *(uint4*)&BsBase[idx] = make_uint4(f2tf(rb[i].x), f2tf(rb[i].y), f2tf(rb[i].z), f2tf(rb[i].w));
    }
    __syncthreads();

    const int KT = DMODEL / TBK;                 // 24
    for (int kt = 0; kt < KT; kt++) {
        const int s = kt & 1;
        const uint32_t* Sa = AsBase + s * STAGE_WORDS;
        const uint32_t* Sb = BsBase + s * STAGE_WORDS;

        if (kt + 1 < KT) {
            const float* ap = Ap + (size_t)(kt + 1) * TBK;
            const float* wp = Wp + (size_t)(kt + 1) * TBK;
            #pragma unroll
            for (int i = 0; i < 4; i++) {
                ra[i] = *(const float4*)(ap + (size_t)i * 32 * DMODEL);
                rb[i] = *(const float4*)(wp + (size_t)i * 32 * DMODEL);
            }
        }

        #pragma unroll
        for (int kk = 0; kk < 4; kk++) {
            const int k0 = kk * 8;
            uint32_t af[4][4];
            #pragma unroll
            for (int mf = 0; mf < 4; mf++) {
                const uint32_t* bp = Sa + (uint32_t)(wm * 64 + mf * 16) * APITCH + k0;
                af[mf][0] = bp[(uint32_t)g * APITCH + tig];
                af[mf][1] = bp[(uint32_t)(g + 8) * APITCH + tig];
                af[mf][2] = bp[(uint32_t)g * APITCH + tig + 4];
                af[mf][3] = bp[(uint32_t)(g + 8) * APITCH + tig + 4];
            }
            uint32_t bf[4][2];
            #pragma unroll
            for (int nf = 0; nf < 4; nf++) {
                const uint32_t* bp = Sb + (uint32_t)(wn * 32 + nf * 8 + g) * APITCH + k0;
                bf[nf][0] = bp[tig];
                bf[nf][1] = bp[tig + 4];
            }
            #pragma unroll
            for (int mf = 0; mf < 4; mf++)
                #pragma unroll
                for (int nf = 0; nf < 4; nf++)
                    mma8(acc[mf][nf], af[mf], bf[nf][0], bf[nf][1]);
        }

        if (kt + 1 < KT) {
            __syncthreads();
            const int s1 = s ^ 1;
            #pragma unroll
            for (int i = 0; i < 4; i++) {
                const uint32_t idx = (uint32_t)(lr + 32 * i) * APITCH + lc;
                *(uint4*)&AsBase[s1 * STAGE_WORDS + idx] =
                    make_uint4(f2tf(ra[i].x), f2tf(ra[i].y), f2tf(ra[i].z), f2tf(ra[i].w));
                *(uint4*)&BsBase[s1 * STAGE_WORDS + idx] =
                    make_uint4(f2tf(rb[i].x), f2tf(rb[i].y), f2tf(rb[i].z), f2tf(rb[i].w));
            }
            __syncthreads();
        }
    }

    // epilogue
    #pragma unroll
    for (int mf = 0; mf < 4; mf++) {
        const int r0 = bm + wm * 64 + mf * 16 + g;
        #pragma unroll
        for (int nf = 0; nf < 4; nf++) {
            const int c = bn + wn * 32 + nf * 8 + tig * 2;
            const float b0 = bias[c], b1 = bias[c + 1];
            const float a0 = acc[mf][nf][0] + b0, a1 = acc[mf][nf][1] + b1;
            const float a2 = acc[mf][nf][2] + b0, a3 = acc[mf][nf][3] + b1;
            if (mode == 0) {
                *(float2*)(C + (size_t)r0 * DMODEL + c) = make_float2(a0, a1);
                *(float2*)(C + (size_t)(r0 + 8) * DMODEL + c) = make_float2(a2, a3);
            } else if (mode == 1) {
                const int h = c >> 6, hd = c & (HD - 1);
                const int bb0 = r0 >> 12, s0r = r0 & (SLEN - 1);
                *(float2*)(C + (((size_t)(bb0 * NH + h)) * SLEN + s0r) * HD + hd) =
                    make_float2(__uint_as_float(f2tf(a0 * scale)),
                                __uint_as_float(f2tf(a1 * scale)));
                const int r1 = r0 + 8;
                const int bb1 = r1 >> 12, s1r = r1 & (SLEN - 1);
                *(float2*)(C + (((size_t)(bb1 * NH + h)) * SLEN + s1r) * HD + hd) =
                    make_float2(__uint_as_float(f2tf(a2 * scale)),
                                __uint_as_float(f2tf(a3 * scale)));
            } else {
                const int h = c >> 6, hd = c & (HD - 1);
                const int bb0 = r0 >> 12, s0r = r0 & (SLEN - 1);
                const int r1 = r0 + 8;
                const int bb1 = r1 >> 12, s1r = r1 & (SLEN - 1);
                __half* vt0 = VT + (((size_t)(bb0 * NH + h)) * HD + hd) * SLEN;
                __half* vt1 = VT + (((size_t)(bb1 * NH + h)) * HD + hd) * SLEN;
                vt0[s0r]        = __float2half_rn(a0);
                vt0[SLEN + s0r] = __float2half_rn(a1);
                vt1[s1r]        = __float2half_rn(a2);
                vt1[SLEN + s1r] = __float2half_rn(a3);
            }
        }
    }
}

// ==================== flash attention: tf32 QK^T + fp16 PV ====================
// Block: 128 thr (4 warps). 128 q-rows/block, 32 q-rows/warp, 64-key tiles.
// Q pre-scaled by log2e/8 (softmax in exp2 domain), Q/K tf32, V fp16 transposed.
// K: row-major pitch 68 (B-frag bank 4g+tig: conflict-free).
// VT: fp16 [hd][key] as u32 words, pitch 36 (B-frag bank 4g+tig: conflict-free).
#define QP 68
#define KP 68
#define VTP 36
#define QS_OFF 0
#define KS_OFF (128 * QP)                  // 8704
#define VS_OFF (KS_OFF + 64 * KP)          // 13056
#define ATT_SMEM_BYTES ((VS_OFF + 64 * VTP) * 4)   // 61440

__global__ __launch_bounds__(128)
void attn_mma_kernel(const float* __restrict__ Qh, const float* __restrict__ Kh,
                     const __half* __restrict__ Vt, float* __restrict__ feats)
{
    extern __shared__ uint32_t sm[];
    const int tid = threadIdx.x, lane = tid & 31, w = tid >> 5;
    const int g = lane >> 2, tig = lane & 3;
    const int bh = blockIdx.y;
    const int qt = gridDim.x - 1 - blockIdx.x;     // LPT: heavy tiles first
    const int q0 = qt * 128;
    const int b = bh / NH, h = bh % NH;
    const size_t base = (size_t)bh * SLEN * HD;
    const __half* vtb = Vt + (size_t)bh * HD * SLEN;
    const int m0 = w * 32;

    const int sr = tid >> 1;                // 0..63 staging row
    const int scb = (tid & 1) * 32;         // staging col offset (words)

    // ---- stage Q tile (128 x 64): straight copy (tf32 + scaled already) ----
    {
        const float4* src = (const float4*)(Qh + base + (size_t)(q0 + tid) * HD);
        float* dst = (float*)sm + QS_OFF + (uint32_t)tid * QP;
        #pragma unroll
        for (int i = 0; i < 16; i++) *(float4*)(dst + i * 4) = src[i];
    }
    __syncthreads();

    // Q fragments resident: 2 mf blocks x 8 kf
    uint32_t qa[2][8][4];
    #pragma unroll
    for (int mf = 0; mf < 2; mf++) {
        const uint32_t rbase = (uint32_t)(m0 + mf * 16);
        #pragma unroll
        for (int kf = 0; kf < 8; kf++) {
            qa[mf][kf][0] = sm[QS_OFF + (rbase + g) * QP + kf * 8 + tig];
            qa[mf][kf][1] = sm[QS_OFF + (rbase + g + 8) * QP + kf * 8 + tig];
            qa[mf][kf][2] = sm[QS_OFF + (rbase + g) * QP + kf * 8 + tig + 4];
            qa[mf][kf][3] = sm[QS_OFF + (rbase + g + 8) * QP + kf * 8 + tig + 4];
        }
    }

    float o[2][8][4];
    #pragma unroll
    for (int mf = 0; mf < 2; mf++)
        #pragma unroll
        for (int nf = 0; nf < 8; nf++)
            #pragma unroll
            for (int t = 0; t < 4; t++) o[mf][nf][t] = 0.f;
    float mr[2][2] = {{-INFINITY, -INFINITY}, {-INFINITY, -INFINITY}};
    float l[2][2] = {{0.f, 0.f}, {0.f, 0.f}};

    const int ntiles = 2 * qt + 2;
    for (int kt = 0; kt < ntiles; kt++) {
        const int k0 = kt * 64;
        // ---- stage K tile (64 x 64 tf32) + VT tile (64 hd x 64 keys fp16) ----
        {
            const float4* ksrc = (const float4*)(Kh + base + (size_t)(k0 + sr) * HD + scb);
            float* kdst = (float*)sm + KS_OFF + (uint32_t)sr * KP + scb;
            #pragma unroll
            for (int i = 0; i < 8; i++) *(float4*)(kdst + i * 4) = ksrc[i];

            // VT: row hd = sr, keys [k0 + (tid&1)*32, +32): 32 fp16 = 64B = 4 float4
            const float4* vsrc = (const float4*)(vtb + (size_t)sr * SLEN + k0 + scb);
            float* vdst = (float*)sm + VS_OFF + (uint32_t)sr * VTP + (tid & 1) * 16;
            #pragma unroll
            for (int i = 0; i < 4; i++) *(float4*)(vdst + i * 4) = vsrc[i];
        }
        __syncthreads();

        const uint32_t* Ksm = sm + KS_OFF;
        const uint32_t* Vsm = sm + VS_OFF;

        const bool active = (k0 <= q0 + m0 + 31);   // warp-uniform
        if (active) {
            // ---- S = Q @ K^T : 32 x 64 per warp (scores in log2 domain) ----
            float sacc[2][8][4];
            #pragma unroll
            for (int mf = 0; mf < 2; mf++)
                #pragma unroll
                for (int nf = 0; nf < 8; nf++)
                    #pragma unroll
                    for (int t = 0; t < 4; t++) sacc[mf][nf][t] = 0.f;
            #pragma unroll
            for (int kf = 0; kf < 8; kf++) {
                #pragma unroll
                for (int nf = 0; nf < 8; nf++) {
                    const uint32_t* bp = Ksm + (uint32_t)(nf * 8 + g) * KP + kf * 8;
                    const uint32_t b0 = bp[tig], b1 = bp[tig + 4];
                    mma8(sacc[0][nf], qa[0][kf], b0, b1);
                    mma8(sacc[1][nf], qa[1][kf], b0, b1);
                }
            }

            // ---- causal mask (only near diagonal) ----
            if (k0 + 63 > q0 + m0) {
                #pragma unroll
                for (int mf = 0; mf < 2; mf++) {
                    const int rA = q0 + m0 + mf * 16 + g;
                    const int rB = rA + 8;
                    #pragma unroll
                    for (int nf = 0; nf < 8; nf++) {
                        const int c0 = k0 + nf * 8 + tig * 2;
                        if (c0 > rA)     sacc[mf][nf][0] = -1e30f;
                        if (c0 + 1 > rA) sacc[mf][nf][1] = -1e30f;
                        if (c0 > rB)     sacc[mf][nf][2] = -1e30f;
                        if (c0 + 1 > rB) sacc[mf][nf][3] = -1e30f;
                    }
                }
            }

            // ---- online softmax (exp2 domain) per mf (rows g, g+8) ----
            #pragma unroll
            for (int mf = 0; mf < 2; mf++) {
                float tm0 = -1e30f, tm1 = -1e30f;
                #pragma unroll
                for (int nf = 0; nf < 8; nf++) {
                    tm0 = fmaxf(tm0, fmaxf(sacc[mf][nf][0], sacc[mf][nf][1]));
                    tm1 = fmaxf(tm1, fmaxf(sacc[mf][nf][2], sacc[mf][nf][3]));
                }
                tm0 = fmaxf(tm0, __shfl_xor_sync(0xffffffffu, tm0, 1));
                tm0 = fmaxf(tm0, __shfl_xor_sync(0xffffffffu, tm0, 2));
                tm1 = fmaxf(tm1, __shfl_xor_sync(0xffffffffu, tm1, 1));
                tm1 = fmaxf(tm1, __shfl_xor_sync(0xffffffffu, tm1, 2));
                const float mn0 = fmaxf(mr[mf][0], tm0), mn1 = fmaxf(mr[mf][1], tm1);
                const float al0 = ex2(mr[mf][0] - mn0), al1 = ex2(mr[mf][1] - mn1);
                mr[mf][0] = mn0; mr[mf][1] = mn1;
                l[mf][0] *= al0; l[mf][1] *= al1;
                #pragma unroll
                for (int nf = 0; nf < 8; nf++) {
                    o[mf][nf][0] *= al0; o[mf][nf][1] *= al0;
                    o[mf][nf][2] *= al1; o[mf][nf][3] *= al1;
                }
                #pragma unroll
                for (int nf = 0; nf < 8; nf++) {
                    const float e0 = ex2(sacc[mf][nf][0] - mn0);
                    const float e1 = ex2(sacc[mf][nf][1] - mn0);
                    const float e2 = ex2(sacc[mf][nf][2] - mn1);
                    const float e3 = ex2(sacc[mf][nf][3] - mn1);
                    l[mf][0] += e0 + e1; l[mf][1] += e2 + e3;
                    sacc[mf][nf][0] = e0; sacc[mf][nf][1] = e1;
                    sacc[mf][nf][2] = e2; sacc[mf][nf][3] = e3;
                }
            }

            // ---- O += P @ V  (fp16 m16n8k16; C-frag packs directly to A-frag) ----
            #pragma unroll
            for (int ks = 0; ks < 4; ks++) {
                uint32_t pa[2][4];
                #pragma unroll
                for (int mf = 0; mf < 2; mf++) {
                    pa[mf][0] = pack_h(sacc[mf][2*ks][0],   sacc[mf][2*ks][1]);
                    pa[mf][1] = pack_h(sacc[mf][2*ks][2],   sacc[mf][2*ks][3]);
                    pa[mf][2] = pack_h(sacc[mf][2*ks+1][0], sacc[mf][2*ks+1][1]);
                    pa[mf][3] = pack_h(sacc[mf][2*ks+1][2], sacc[mf][2*ks+1][3]);
                }
                #pragma unroll
                for (int nf = 0; nf < 8; nf++) {
                    const uint32_t* bp = Vsm + (uint32_t)(nf * 8 + g) * VTP + ks * 8 + tig;
                    const uint32_t b0 = bp[0], b1 = bp[4];
                    mma16h(o[0][nf], pa[0], b0, b1);
                    mma16h(o[1][nf], pa[1], b0, b1);
                }
            }
        }
        __syncthreads();
    }

    // ---- finalize ----
    #pragma unroll
    for (int mf = 0; mf < 2; mf++) {
        float l0 = l[mf][0], l1 = l[mf][1];
        l0 += __shfl_xor_sync(0xffffffffu, l0, 1);
        l0 += __shfl_xor_sync(0xffffffffu, l0, 2);
        l1 += __shfl_xor_sync(0xffffffffu, l1, 1);
        l1 += __shfl_xor_sync(0xffffffffu, l1, 2);
        const float i0 = 1.f / l0, i1 = 1.f / l1;
        const int r0 = q0 + m0 + mf * 16 + g;
        #pragma unroll
        for (int nf = 0; nf < 8; nf++) {
            const int col = h * HD + nf * 8 + tig * 2;
            *(float2*)(feats + ((size_t)(b * SLEN + r0)) * DMODEL + col) =
                make_float2(o[mf][nf][0] * i0, o[mf][nf][1] * i0);
            *(float2*)(feats + ((size_t)(b * SLEN + r0 + 8)) * DMODEL + col) =
                make_float2(o[mf][nf][2] * i1, o[mf][nf][3] * i1);
        }
    }
}

// ==================== launch ====================
extern "C" void kernel_launch(void* const* d_in, const int* in_sizes, int n_in,
                              void* d_out, int out_size)
{
    const float* q  = (const float*)d_in[0];
    const float* k  = (const float*)d_in[1];
    const float* v  = (const float*)d_in[2];
    // d_in[3] = mask (always causal triu(k=1); handled analytically)
    const float* Wq = (const float*)d_in[4];
    const float* bq = (const float*)d_in[5];
    const float* Wk = (const float*)d_in[6];
    const float* bk = (const float*)d_in[7];
    const float* Wv = (const float*)d_in[8];
    const float* bv = (const float*)d_in[9];
    const float* Wo = (const float*)d_in[10];
    const float* bo = (const float*)d_in[11];

    float *qh, *kh, *feats;
    __half* vt;
    cudaGetSymbolAddress((void**)&qh, g_qh);
    cudaGetSymbolAddress((void**)&kh, g_kh);
    cudaGetSymbolAddress((void**)&vt, g_vt);
    cudaGetSymbolAddress((void**)&feats, g_feats);

    cudaFuncSetAttribute(mma_gemm_kernel,
                         cudaFuncAttributeMaxDynamicSharedMemorySize, GEMM_SMEM);
    cudaFuncSetAttribute(attn_mma_kernel,
                         cudaFuncAttributeMaxDynamicSharedMemorySize, ATT_SMEM_BYTES);

    const float qscale = 0.125f * 1.4426950408889634f;   // (1/sqrt(64)) * log2(e)

    dim3 gg(DMODEL / 128, MROWS / 128);   // (6, 64)
    mma_gemm_kernel<<<gg, 256, GEMM_SMEM>>>(q, Wq, bq, qh, nullptr, 1, qscale);
    mma_gemm_kernel<<<gg, 256, GEMM_SMEM>>>(k, Wk, bk, kh, nullptr, 1, 1.0f);
    mma_gemm_kernel<<<gg, 256, GEMM_SMEM>>>(v, Wv, bv, nullptr, vt, 2, 1.0f);

    attn_mma_kernel<<<dim3(SLEN / 128, BATCH * NH), 128, ATT_SMEM_BYTES>>>(qh, kh, vt, feats);

    mma_gemm_kernel<<<gg, 256, GEMM_SMEM>>>(feats, Wo, bo, (float*)d_out, nullptr, 0, 1.0f);
}

// round 14
// speedup vs baseline: 2.1672x; 1.5676x over previous
#include <cuda_runtime.h>
#include <cuda_fp16.h>
#include <math.h>
#include <stdint.h>

// Problem constants
#define BATCH 2
#define SLEN  4096
#define DMODEL 768
#define NH    12
#define HD    64
#define MROWS (BATCH * SLEN)        // 8192

// ---------------- scratch (device globals; allocation-free) ----------------
__device__ __half g_qh[BATCH * NH * SLEN * HD];  // [B,H,S,HD] fp16, pre-scaled by log2e/8
__device__ __half g_kh[BATCH * NH * SLEN * HD];  // [B,H,S,HD] fp16
__device__ __half g_vt[BATCH * NH * HD * SLEN];  // [B,H,HD,S] fp16 (transposed)
__device__ float g_feats[BATCH * SLEN * DMODEL]; // [B,S,D]

// ==================== helpers ====================
__device__ __forceinline__ float ex2(float x) {
    float r;
    asm("ex2.approx.f32 %0, %1;" : "=f"(r) : "f"(x));
    return r;
}
// pack two f32 into f16x2: lo <- a, hi <- b
__device__ __forceinline__ uint32_t pack_h(float a, float b) {
    uint32_t r;
    asm("cvt.rn.f16x2.f32 %0, %1, %2;" : "=r"(r) : "f"(b), "f"(a));
    return r;
}
// fp16: D(16x8) = A(16x16) @ B(16x8) + D, f32 accum
__device__ __forceinline__ void mma16h(float* c, const uint32_t* a,
                                       uint32_t b0, uint32_t b1) {
    asm volatile(
        "mma.sync.aligned.m16n8k16.row.col.f32.f16.f16.f32 "
        "{%0,%1,%2,%3}, {%4,%5,%6,%7}, {%8,%9}, {%0,%1,%2,%3};"
        : "+f"(c[0]), "+f"(c[1]), "+f"(c[2]), "+f"(c[3])
        : "r"(a[0]), "r"(a[1]), "r"(a[2]), "r"(a[3]), "r"(b0), "r"(b1));
}

// ==================== fp16 mma.sync GEMM: C = X @ W^T + bias ====================
// A/W staged as fp16 (f32 accum). CTA 128x128, BK=32, 8 warps (64x32 warp tile).
// mode 0: C[m*768+n] plain fp32.
// mode 1: split-head fp16 scatter to H[B,H,S,HD], value = fp16((acc+bias)*scale).
// mode 2: fp16 transposed scatter to H as VT[B,H,HD,S].
#define TBK 32
#define HP 20                               // words per 32-k row (16 + 4 pad)
#define HSTAGE (128 * HP)                   // 2560 words per matrix per stage
#define GEMM_SMEM (4 * HSTAGE * 4)          // 40960 B

__global__ __launch_bounds__(256)
void mma_gemm_kernel(const float* __restrict__ A, const float* __restrict__ W,
                     const float* __restrict__ bias, float* __restrict__ C,
                     __half* __restrict__ H, int mode, float scale)
{
    extern __shared__ uint32_t sm[];
    uint32_t* AsBase = sm;                  // [2][HSTAGE]
    uint32_t* BsBase = sm + 2 * HSTAGE;     // [2][HSTAGE]

    const int tid  = threadIdx.x;
    const int lane = tid & 31, wid = tid >> 5;
    const int g = lane >> 2, tig = lane & 3;
    const int wm = wid >> 2, wn = wid & 3;  // 2 x 4 warp grid
    const int bm = blockIdx.y * 128, bn = blockIdx.x * 128;

    const int lr = tid >> 3;                // 0..31
    const int lc = (tid & 7) * 4;           // 0,4,...,28 (f32 col)
    const int wc = (tid & 7) * 2;           // word col in fp16 tile
    const float* Ap = A + (size_t)(bm + lr) * DMODEL + lc;
    const float* Wp = W + (size_t)(bn + lr) * DMODEL + lc;

    float acc[4][4][4];
    #pragma unroll
    for (int i = 0; i < 4; i++)
        #pragma unroll
        for (int j = 0; j < 4; j++)
            #pragma unroll
            for (int t = 0; t < 4; t++) acc[i][j][t] = 0.f;

    float4 ra[4], rb[4];
    #pragma unroll
    for (int i = 0; i < 4; i++) {
        ra[i] = *(const float4*)(Ap + (size_t)i * 32 * DMODEL);
        rb[i] = *(const float4*)(Wp + (size_t)i * 32 * DMODEL);
    }
    #pragma unroll
    for (int i = 0; i < 4; i++) {
        const uint32_t idx = (uint32_t)(lr + 32 * i) * HP + wc;
        *(uint2*)&AsBase[idx] = make_uint2(pack_h(ra[i].x, ra[i].y), pack_h(ra[i].z, ra[i].w));
        *(uint2*)&BsBase[idx] = make_uint2(pack_h(rb[i].x, rb[i].y), pack_h(rb[i].z, rb[i].w));
    }
    __syncthreads();

    const int KT = DMODEL / TBK;            // 24
    for (int kt = 0; kt < KT; kt++) {
        const int s = kt & 1;
        const uint32_t* Sa = AsBase + s * HSTAGE;
        const uint32_t* Sb = BsBase + s * HSTAGE;

        if (kt + 1 < KT) {
            const float* ap = Ap + (size_t)(kt + 1) * TBK;
            const float* wp = Wp + (size_t)(kt + 1) * TBK;
            #pragma unroll
            for (int i = 0; i < 4; i++) {
                ra[i] = *(const float4*)(ap + (size_t)i * 32 * DMODEL);
                rb[i] = *(const float4*)(wp + (size_t)i * 32 * DMODEL);
            }
        }

        #pragma unroll
        for (int ks = 0; ks < 2; ks++) {
            const int k0 = ks * 8;
            uint32_t af[4][4];
            #pragma unroll
            for (int mf = 0; mf < 4; mf++) {
                const uint32_t* bp = Sa + (uint32_t)(wm * 64 + mf * 16) * HP + k0;
                af[mf][0] = bp[(uint32_t)g * HP + tig];
                af[mf][1] = bp[(uint32_t)(g + 8) * HP + tig];
                af[mf][2] = bp[(uint32_t)g * HP + tig + 4];
                af[mf][3] = bp[(uint32_t)(g + 8) * HP + tig + 4];
            }
            uint32_t bf[4][2];
            #pragma unroll
            for (int nf = 0; nf < 4; nf++) {
                const uint32_t* bp = Sb + (uint32_t)(wn * 32 + nf * 8 + g) * HP + k0;
                bf[nf][0] = bp[tig];
                bf[nf][1] = bp[tig + 4];
            }
            #pragma unroll
            for (int mf = 0; mf < 4; mf++)
                #pragma unroll
                for (int nf = 0; nf < 4; nf++)
                    mma16h(acc[mf][nf], af[mf], bf[nf][0], bf[nf][1]);
        }

        if (kt + 1 < KT) {
            __syncthreads();
            const int s1 = s ^ 1;
            #pragma unroll
            for (int i = 0; i < 4; i++) {
                const uint32_t idx = (uint32_t)(lr + 32 * i) * HP + wc;
                *(uint2*)&AsBase[s1 * HSTAGE + idx] =
                    make_uint2(pack_h(ra[i].x, ra[i].y), pack_h(ra[i].z, ra[i].w));
                *(uint2*)&BsBase[s1 * HSTAGE + idx] =
                    make_uint2(pack_h(rb[i].x, rb[i].y), pack_h(rb[i].z, rb[i].w));
            }
            __syncthreads();
        }
    }

    // epilogue
    #pragma unroll
    for (int mf = 0; mf < 4; mf++) {
        const int r0 = bm + wm * 64 + mf * 16 + g;
        #pragma unroll
        for (int nf = 0; nf < 4; nf++) {
            const int c = bn + wn * 32 + nf * 8 + tig * 2;
            const float b0 = bias[c], b1 = bias[c + 1];
            const float a0 = acc[mf][nf][0] + b0, a1 = acc[mf][nf][1] + b1;
            const float a2 = acc[mf][nf][2] + b0, a3 = acc[mf][nf][3] + b1;
            if (mode == 0) {
                *(float2*)(C + (size_t)r0 * DMODEL + c) = make_float2(a0, a1);
                *(float2*)(C + (size_t)(r0 + 8) * DMODEL + c) = make_float2(a2, a3);
            } else if (mode == 1) {
                const int h = c >> 6, hd = c & (HD - 1);
                const int bb0 = r0 >> 12, s0r = r0 & (SLEN - 1);
                *(uint32_t*)(H + (((size_t)(bb0 * NH + h)) * SLEN + s0r) * HD + hd) =
                    pack_h(a0 * scale, a1 * scale);
                const int r1 = r0 + 8;
                const int bb1 = r1 >> 12, s1r = r1 & (SLEN - 1);
                *(uint32_t*)(H + (((size_t)(bb1 * NH + h)) * SLEN + s1r) * HD + hd) =
                    pack_h(a2 * scale, a3 * scale);
            } else {
                const int h = c >> 6, hd = c & (HD - 1);
                const int bb0 = r0 >> 12, s0r = r0 & (SLEN - 1);
                const int r1 = r0 + 8;
                const int bb1 = r1 >> 12, s1r = r1 & (SLEN - 1);
                __half* vt0 = H + (((size_t)(bb0 * NH + h)) * HD + hd) * SLEN;
                __half* vt1 = H + (((size_t)(bb1 * NH + h)) * HD + hd) * SLEN;
                vt0[s0r]        = __float2half_rn(a0);
                vt0[SLEN + s0r] = __float2half_rn(a1);
                vt1[s1r]        = __float2half_rn(a2);
                vt1[SLEN + s1r] = __float2half_rn(a3);
            }
        }
    }
}

// ==================== flash attention: full fp16 mma (f32 accum) ====================
// Block: 128 thr (4 warps). 128 q-rows/block, 32 q-rows/warp, 64-key tiles.
// Q pre-scaled by log2e/8 (exp2-domain softmax). All operands fp16, pitch 36
// (word bank = 4g + 8ks + tig: conflict-free for all fragment loads).
#define QP2 36
#define KP2 36
#define VTP 36
#define QS_OFF 0
#define KS_OFF (128 * QP2)                 // 4608
#define VS_OFF (KS_OFF + 64 * KP2)         // 6912
#define ATT_SMEM_BYTES ((VS_OFF + 64 * VTP) * 4)   // 36864

__global__ __launch_bounds__(128)
void attn_mma_kernel(const __half* __restrict__ Qh, const __half* __restrict__ Kh,
                     const __half* __restrict__ Vt, float* __restrict__ feats)
{
    extern __shared__ uint32_t sm[];
    const int tid = threadIdx.x, lane = tid & 31, w = tid >> 5;
    const int g = lane >> 2, tig = lane & 3;
    const int bh = blockIdx.y;
    const int qt = gridDim.x - 1 - blockIdx.x;     // LPT: heavy tiles first
    const int q0 = qt * 128;
    const int b = bh / NH, h = bh % NH;
    const size_t base = (size_t)bh * SLEN * HD;
    const __half* vtb = Vt + (size_t)bh * HD * SLEN;
    const int m0 = w * 32;

    const int sr = tid >> 1;                // 0..63 staging row
    const int sh = tid & 1;                 // staging half

    // ---- stage Q tile (128 rows x 64 fp16 = 32 words) ----
    {
        const float4* src = (const float4*)(Qh + base + (size_t)(q0 + tid) * HD);
        float* dst = (float*)sm + QS_OFF + (uint32_t)tid * QP2;
        #pragma unroll
        for (int i = 0; i < 8; i++) *(float4*)(dst + i * 4) = src[i];
    }
    __syncthreads();

    // Q fragments resident: 2 mf x 4 ks (fp16 m16n8k16 A-frags)
    uint32_t qa[2][4][4];
    #pragma unroll
    for (int mf = 0; mf < 2; mf++) {
        const uint32_t rbase = (uint32_t)(m0 + mf * 16);
        #pragma unroll
        for (int ks = 0; ks < 4; ks++) {
            qa[mf][ks][0] = sm[QS_OFF + (rbase + g) * QP2 + ks * 8 + tig];
            qa[mf][ks][1] = sm[QS_OFF + (rbase + g + 8) * QP2 + ks * 8 + tig];
            qa[mf][ks][2] = sm[QS_OFF + (rbase + g) * QP2 + ks * 8 + tig + 4];
            qa[mf][ks][3] = sm[QS_OFF + (rbase + g + 8) * QP2 + ks * 8 + tig + 4];
        }
    }

    float o[2][8][4];
    #pragma unroll
    for (int mf = 0; mf < 2; mf++)
        #pragma unroll
        for (int nf = 0; nf < 8; nf++)
            #pragma unroll
            for (int t = 0; t < 4; t++) o[mf][nf][t] = 0.f;
    float mr[2][2] = {{-INFINITY, -INFINITY}, {-INFINITY, -INFINITY}};
    float l[2][2] = {{0.f, 0.f}, {0.f, 0.f}};

    const int ntiles = 2 * qt + 2;
    for (int kt = 0; kt < ntiles; kt++) {
        const int k0 = kt * 64;
        // ---- stage K tile (64 x 64 fp16) + VT tile (64 hd x 64 keys fp16) ----
        {
            const float4* ksrc = (const float4*)(Kh + base + (size_t)(k0 + sr) * HD + sh * 32);
            float* kdst = (float*)sm + KS_OFF + (uint32_t)sr * KP2 + sh * 16;
            #pragma unroll
            for (int i = 0; i < 4; i++) *(float4*)(kdst + i * 4) = ksrc[i];

            const float4* vsrc = (const float4*)(vtb + (size_t)sr * SLEN + k0 + sh * 32);
            float* vdst = (float*)sm + VS_OFF + (uint32_t)sr * VTP + sh * 16;
            #pragma unroll
            for (int i = 0; i < 4; i++) *(float4*)(vdst + i * 4) = vsrc[i];
        }
        __syncthreads();

        const uint32_t* Ksm = sm + KS_OFF;
        const uint32_t* Vsm = sm + VS_OFF;

        const bool active = (k0 <= q0 + m0 + 31);   // warp-uniform
        if (active) {
            // ---- S = Q @ K^T : 32 x 64 per warp (fp16 mma, log2-domain scores) ----
            float sacc[2][8][4];
            #pragma unroll
            for (int mf = 0; mf < 2; mf++)
                #pragma unroll
                for (int nf = 0; nf < 8; nf++)
                    #pragma unroll
                    for (int t = 0; t < 4; t++) sacc[mf][nf][t] = 0.f;
            #pragma unroll
            for (int ks = 0; ks < 4; ks++) {
                #pragma unroll
                for (int nf = 0; nf < 8; nf++) {
                    const uint32_t* bp = Ksm + (uint32_t)(nf * 8 + g) * KP2 + ks * 8;
                    const uint32_t b0 = bp[tig], b1 = bp[tig + 4];
                    mma16h(sacc[0][nf], qa[0][ks], b0, b1);
                    mma16h(sacc[1][nf], qa[1][ks], b0, b1);
                }
            }

            // ---- causal mask (only near diagonal) ----
            if (k0 + 63 > q0 + m0) {
                #pragma unroll
                for (int mf = 0; mf < 2; mf++) {
                    const int rA = q0 + m0 + mf * 16 + g;
                    const int rB = rA + 8;
                    #pragma unroll
                    for (int nf = 0; nf < 8; nf++) {
                        const int c0 = k0 + nf * 8 + tig * 2;
                        if (c0 > rA)     sacc[mf][nf][0] = -1e30f;
                        if (c0 + 1 > rA) sacc[mf][nf][1] = -1e30f;
                        if (c0 > rB)     sacc[mf][nf][2] = -1e30f;
                        if (c0 + 1 > rB) sacc[mf][nf][3] = -1e30f;
                    }
                }
            }

            // ---- online softmax (exp2 domain) per mf (rows g, g+8) ----
            #pragma unroll
            for (int mf = 0; mf < 2; mf++) {
                float tm0 = -1e30f, tm1 = -1e30f;
                #pragma unroll
                for (int nf = 0; nf < 8; nf++) {
                    tm0 = fmaxf(tm0, fmaxf(sacc[mf][nf][0], sacc[mf][nf][1]));
                    tm1 = fmaxf(tm1, fmaxf(sacc[mf][nf][2], sacc[mf][nf][3]));
                }
                tm0 = fmaxf(tm0, __shfl_xor_sync(0xffffffffu, tm0, 1));
                tm0 = fmaxf(tm0, __shfl_xor_sync(0xffffffffu, tm0, 2));
                tm1 = fmaxf(tm1, __shfl_xor_sync(0xffffffffu, tm1, 1));
                tm1 = fmaxf(tm1, __shfl_xor_sync(0xffffffffu, tm1, 2));
                const float mn0 = fmaxf(mr[mf][0], tm0), mn1 = fmaxf(mr[mf][1], tm1);
                const float al0 = ex2(mr[mf][0] - mn0), al1 = ex2(mr[mf][1] - mn1);
                mr[mf][0] = mn0; mr[mf][1] = mn1;
                l[mf][0] *= al0; l[mf][1] *= al1;
                #pragma unroll
                for (int nf = 0; nf < 8; nf++) {
                    o[mf][nf][0] *= al0; o[mf][nf][1] *= al0;
                    o[mf][nf][2] *= al1; o[mf][nf][3] *= al1;
                }
                #pragma unroll
                for (int nf = 0; nf < 8; nf++) {
                    const float e0 = ex2(sacc[mf][nf][0] - mn0);
                    const float e1 = ex2(sacc[mf][nf][1] - mn0);
                    const float e2 = ex2(sacc[mf][nf][2] - mn1);
                    const float e3 = ex2(sacc[mf][nf][3] - mn1);
                    l[mf][0] += e0 + e1; l[mf][1] += e2 + e3;
                    sacc[mf][nf][0] = e0; sacc[mf][nf][1] = e1;
                    sacc[mf][nf][2] = e2; sacc[mf][nf][3] = e3;
                }
            }

            // ---- O += P @ V  (fp16 m16n8k16; C-frag packs directly to A-frag) ----
            #pragma unroll
            for (int ks = 0; ks < 4; ks++) {
                uint32_t pa[2][4];
                #pragma unroll
                for (int mf = 0; mf < 2; mf++) {
                    pa[mf][0] = pack_h(sacc[mf][2*ks][0],   sacc[mf][2*ks][1]);
                    pa[mf][1] = pack_h(sacc[mf][2*ks][2],   sacc[mf][2*ks][3]);
                    pa[mf][2] = pack_h(sacc[mf][2*ks+1][0], sacc[mf][2*ks+1][1]);
                    pa[mf][3] = pack_h(sacc[mf][2*ks+1][2], sacc[mf][2*ks+1][3]);
                }
                #pragma unroll
                for (int nf = 0; nf < 8; nf++) {
                    const uint32_t* bp = Vsm + (uint32_t)(nf * 8 + g) * VTP + ks * 8 + tig;
                    const uint32_t b0 = bp[0], b1 = bp[4];
                    mma16h(o[0][nf], pa[0], b0, b1);
                    mma16h(o[1][nf], pa[1], b0, b1);
                }
            }
        }
        __syncthreads();
    }

    // ---- finalize ----
    #pragma unroll
    for (int mf = 0; mf < 2; mf++) {
        float l0 = l[mf][0], l1 = l[mf][1];
        l0 += __shfl_xor_sync(0xffffffffu, l0, 1);
        l0 += __shfl_xor_sync(0xffffffffu, l0, 2);
        l1 += __shfl_xor_sync(0xffffffffu, l1, 1);
        l1 += __shfl_xor_sync(0xffffffffu, l1, 2);
        const float i0 = 1.f / l0, i1 = 1.f / l1;
        const int r0 = q0 + m0 + mf * 16 + g;
        #pragma unroll
        for (int nf = 0; nf < 8; nf++) {
            const int col = h * HD + nf * 8 + tig * 2;
            *(float2*)(feats + ((size_t)(b * SLEN + r0)) * DMODEL + col) =
                make_float2(o[mf][nf][0] * i0, o[mf][nf][1] * i0);
            *(float2*)(feats + ((size_t)(b * SLEN + r0 + 8)) * DMODEL + col) =
                make_float2(o[mf][nf][2] * i1, o[mf][nf][3] * i1);
        }
    }
}

// ==================== launch ====================
extern "C" void kernel_launch(void* const* d_in, const int* in_sizes, int n_in,
                              void* d_out, int out_size)
{
    const float* q  = (const float*)d_in[0];
    const float* k  = (const float*)d_in[1];
    const float* v  = (const float*)d_in[2];
    // d_in[3] = mask (always causal triu(k=1); handled analytically)
    const float* Wq = (const float*)d_in[4];
    const float* bq = (const float*)d_in[5];
    const float* Wk = (const float*)d_in[6];
    const float* bk = (const float*)d_in[7];
    const float* Wv = (const float*)d_in[8];
    const float* bv = (const float*)d_in[9];
    const float* Wo = (const float*)d_in[10];
    const float* bo = (const float*)d_in[11];

    __half *qh, *kh, *vt;
    float *feats;
    cudaGetSymbolAddress((void**)&qh, g_qh);
    cudaGetSymbolAddress((void**)&kh, g_kh);
    cudaGetSymbolAddress((void**)&vt, g_vt);
    cudaGetSymbolAddress((void**)&feats, g_feats);

    cudaFuncSetAttribute(mma_gemm_kernel,
                         cudaFuncAttributeMaxDynamicSharedMemorySize, GEMM_SMEM);
    cudaFuncSetAttribute(attn_mma_kernel,
                         cudaFuncAttributeMaxDynamicSharedMemorySize, ATT_SMEM_BYTES);

    const float qscale = 0.125f * 1.4426950408889634f;   // (1/sqrt(64)) * log2(e)

    dim3 gg(DMODEL / 128, MROWS / 128);   // (6, 64)
    mma_gemm_kernel<<<gg, 256, GEMM_SMEM>>>(q, Wq, bq, nullptr, qh, 1, qscale);
    mma_gemm_kernel<<<gg, 256, GEMM_SMEM>>>(k, Wk, bk, nullptr, kh, 1, 1.0f);
    mma_gemm_kernel<<<gg, 256, GEMM_SMEM>>>(v, Wv, bv, nullptr, vt, 2, 1.0f);

    attn_mma_kernel<<<dim3(SLEN / 128, BATCH * NH), 128, ATT_SMEM_BYTES>>>(qh, kh, vt, feats);

    mma_gemm_kernel<<<gg, 256, GEMM_SMEM>>>(feats, Wo, bo, (float*)d_out, nullptr, 0, 1.0f);
}